// round 14
// baseline (speedup 1.0000x reference)
#include <cuda_runtime.h>

#define CCH 32
#define HH 48
#define WW 48
#define DDD 48
#define PDW 56
#define RD2 56
#define X1S_ROW 48                       // floats per x1-scratch row (packed 192B)
#define X1S_W 64                         // w rows per (c,h): w+8, covers w in [-8,55]
#define X1S_CSTRIDE (48 * X1S_W * X1S_ROW)   // 147456
#define X2P_CSTRIDE (56 * 56 * RD2)          // 175616
#define OUT_CSTRIDE (48 * 48 * 48)           // 110592

typedef unsigned long long ull;

// x1 guard-banded copy: (C, h, wp=w+8 in 0..63, 48 fl rows). OOB w -> 0.
__device__ float g_x1p[CCH * 48 * X1S_W * X1S_ROW];
// Zero-padded x2 copy: (C, h+4, w+4, d'=d+4 in 56-float rows).
__device__ float g_x2p[CCH * PDW * PDW * RD2];

__global__ void pad1_kernel(const float* __restrict__ x1) {
    int idx = blockIdx.x * blockDim.x + threadIdx.x;
    const int total = CCH * 48 * X1S_W * (X1S_ROW / 4);
    if (idx >= total) return;
    int d4 = idx % 12;
    int t = idx / 12;
    int wp = t % X1S_W; t /= X1S_W;
    int h = t % 48;
    int c = t / 48;
    int w = wp - 8;
    float4 v = make_float4(0.f, 0.f, 0.f, 0.f);
    if ((unsigned)w < (unsigned)WW)
        v = *(const float4*)(x1 + ((c * HH + h) * WW + w) * DDD + d4 * 4);
    *(float4*)(g_x1p + (size_t)idx * 4) = v;
}

__global__ void pad2_kernel(const float* __restrict__ x2) {
    int idx = blockIdx.x * blockDim.x + threadIdx.x;
    const int total = CCH * PDW * PDW * (RD2 / 4);
    if (idx >= total) return;
    int f4 = idx % (RD2 / 4);
    int t = idx / (RD2 / 4);
    int wp = t % PDW; t /= PDW;
    int hp = t % PDW;
    int c = t / PDW;
    int w = wp - 4, h = hp - 4;
    float4 v = make_float4(0.f, 0.f, 0.f, 0.f);
    if ((unsigned)h < (unsigned)HH && (unsigned)w < (unsigned)WW && f4 >= 1 && f4 <= 12)
        v = *(const float4*)(x2 + ((c * HH + h) * WW + w) * DDD + (f4 - 1) * 4);
    *(float4*)(g_x2p + (size_t)idx * 4) = v;
}

__device__ __forceinline__ void fma2(ull& a, ull x, ull y) {
    asm("fma.rn.f32x2 %0, %1, %2, %0;" : "+l"(a) : "l"(x), "l"(y));
}
__device__ __forceinline__ void upk2(ull v, float& lo, float& hi) {
    asm("mov.b64 {%0, %1}, %2;" : "=f"(lo), "=f"(hi) : "l"(v));
}
// (hi32(a), lo32(b)) as packed f32x2 — register-pair select, 2 MOVs max.
__device__ __forceinline__ ull selpair(ull a, ull b) {
    float alo, ahi, blo, bhi;
    upk2(a, alo, ahi);
    upk2(b, blo, bhi);
    ull r;
    asm("mov.b64 %0, {%1, %2};" : "=l"(r) : "f"(ahi), "f"(blo));
    return r;
}

// Diagonal-blocked, barrier-free. CTA = (h, 8-row band of x2 rows, di, dj-group).
// Thread: chunk=t%12 -> D=4*chunk; rl=t/12 -> x2 row sp=s0+rl.
// JC diagonals per thread: outputs (w_j = sp - dj0 - j, dj0+j), j=0..JC-1,
// all 9 dk, 4 d voxels. One 12-float B window feeds JC*18 FFMA2.
// B double-buffered (L2-resident scratch); A loaded just-in-time (L1-warm,
// guard-banded scratch so p1b - 48*j is always in-bounds).
template <int JC>
__global__ __launch_bounds__(96, (JC == 4) ? 3 : 6)
void corr_main(float* __restrict__ out) {
    int di, dj0;
    if (JC == 4) {
        di = blockIdx.y >> 1;           // 0..8
        dj0 = (blockIdx.y & 1) * 4;     // 0 or 4
    } else {
        di = blockIdx.y;                // 0..8
        dj0 = 8;
    }

    const int bx = blockIdx.x;          // 0..335
    const int h  = bx / 7;
    const int s0 = (bx % 7) * 8;

    const int t = threadIdx.x;          // 0..95
    const int chunk = t % 12;
    const int rl = t / 12;
    const int D = chunk * 4;
    const int sp = s0 + rl;             // x2 scratch row 0..55

    const float* p1b = g_x1p + (h * X1S_W + (sp - dj0 + 8)) * X1S_ROW + D;
    const float* p2  = g_x2p + ((h + di) * PDW + sp) * RD2 + D;

    bool vj[JC];
#pragma unroll
    for (int j = 0; j < JC; j++)
        vj[j] = ((unsigned)(sp - dj0 - j) < (unsigned)WW);

    ull acc[JC][2][9];
#pragma unroll
    for (int j = 0; j < JC; j++)
#pragma unroll
        for (int p = 0; p < 2; p++)
#pragma unroll
            for (int k = 0; k < 9; k++) acc[j][p][k] = 0ull;

    ulonglong2 A[JC];
    ulonglong2 B0[3], B1[3];

#define LOADB(Bbuf)                                                                \
    do {                                                                           \
        Bbuf[0] = *(const ulonglong2*)(p2);                                        \
        Bbuf[1] = *(const ulonglong2*)(p2 + 4);                                    \
        Bbuf[2] = *(const ulonglong2*)(p2 + 8);                                    \
        p2 += X2P_CSTRIDE;                                                         \
    } while (0)

#define LOADA()                                                                    \
    do {                                                                           \
        _Pragma("unroll")                                                          \
        for (int j = 0; j < JC; j++)                                               \
            A[j] = *(const ulonglong2*)(p1b - 48 * j);                             \
        p1b += X1S_CSTRIDE;                                                        \
    } while (0)

#define COMPUTECH(Bbuf)                                                            \
    do {                                                                           \
        ull P[6];                                                                  \
        P[0] = Bbuf[0].x; P[1] = Bbuf[0].y;                                        \
        P[2] = Bbuf[1].x; P[3] = Bbuf[1].y;                                        \
        P[4] = Bbuf[2].x; P[5] = Bbuf[2].y;                                        \
        ull S[5];                                                                  \
        S[0] = selpair(P[0], P[1]); S[1] = selpair(P[1], P[2]);                    \
        S[2] = selpair(P[2], P[3]); S[3] = selpair(P[3], P[4]);                    \
        S[4] = selpair(P[4], P[5]);                                                \
        _Pragma("unroll")                                                          \
        for (int j = 0; j < JC; j++) {                                             \
            const ull Aj0 = A[j].x, Aj1 = A[j].y;                                  \
            _Pragma("unroll")                                                      \
            for (int dk = 0; dk < 9; dk++) {                                       \
                const int m = dk >> 1;                                             \
                if (dk & 1) {                                                      \
                    fma2(acc[j][0][dk], Aj0, S[m]);                                \
                    fma2(acc[j][1][dk], Aj1, S[m + 1]);                            \
                } else {                                                           \
                    fma2(acc[j][0][dk], Aj0, P[m]);                                \
                    fma2(acc[j][1][dk], Aj1, P[m + 1]);                            \
                }                                                                  \
            }                                                                      \
        }                                                                          \
    } while (0)

    LOADB(B0);
#pragma unroll 1
    for (int c = 0; c < CCH; c += 2) {
        LOADA();
        LOADB(B1);
        COMPUTECH(B0);
        LOADA();
        if (c + 2 < CCH) LOADB(B0);
        COMPUTECH(B1);
    }

    // epilogue: dense predicated stores (chunk fastest across warp)
    const float inv = 1.0f / 32.0f;
#pragma unroll
    for (int j = 0; j < JC; j++) {
        if (!vj[j]) continue;
        const size_t ob = (size_t)((h * WW + (sp - dj0 - j)) * DDD + D);
        const int pl0 = (di * 9 + dj0 + j) * 9;
#pragma unroll
        for (int dk = 0; dk < 9; dk++) {
            float l0, h0, l1, h1;
            upk2(acc[j][0][dk], l0, h0);
            upk2(acc[j][1][dk], l1, h1);
            *(float4*)(out + (size_t)(pl0 + dk) * OUT_CSTRIDE + ob) =
                make_float4(l0 * inv, h0 * inv, l1 * inv, h1 * inv);
        }
    }
#undef LOADB
#undef LOADA
#undef COMPUTECH
}

extern "C" void kernel_launch(void* const* d_in, const int* in_sizes, int n_in,
                              void* d_out, int out_size) {
    const float* x1 = (const float*)d_in[0];
    const float* x2 = (const float*)d_in[1];
    float* out = (float*)d_out;

    const int t1 = CCH * 48 * X1S_W * (X1S_ROW / 4);
    pad1_kernel<<<(t1 + 255) / 256, 256>>>(x1);
    const int t2 = CCH * PDW * PDW * (RD2 / 4);
    pad2_kernel<<<(t2 + 255) / 256, 256>>>(x2);

    dim3 g4(336, 18);   // dj groups {0..3}, {4..7}
    corr_main<4><<<g4, 96>>>(out);
    dim3 g1(336, 9);    // dj = 8
    corr_main<1><<<g1, 96>>>(out);
}

// round 16
// speedup vs baseline: 2.3050x; 2.3050x over previous
#include <cuda_runtime.h>

#define CCH 32
#define HH 48
#define WW 48
#define DDD 48
#define PDW 56
#define RD2 56                          // x2 scratch row length in floats (224B, packed)
#define X1_CSTRIDE (48 * 48 * 48)       // 110592
#define X2P_CSTRIDE (56 * 56 * RD2)     // 175616
#define OUT_CSTRIDE (48 * 48 * 48)      // 110592

typedef unsigned long long ull;

// Zero-padded x2 copy: (C, h+4, w+4, d'=d+4 in 56-float rows), PRE-SCALED by 1/32.
__device__ float g_x2p[CCH * PDW * PDW * RD2];

__global__ void pad2_kernel(const float* __restrict__ x2) {
    int idx = blockIdx.x * blockDim.x + threadIdx.x;
    const int total = CCH * PDW * PDW * (RD2 / 4);
    if (idx >= total) return;
    int f4 = idx % (RD2 / 4);
    int t = idx / (RD2 / 4);
    int wp = t % PDW; t /= PDW;
    int hp = t % PDW;
    int c = t / PDW;
    int w = wp - 4, h = hp - 4;
    float4 v = make_float4(0.f, 0.f, 0.f, 0.f);
    if ((unsigned)h < (unsigned)HH && (unsigned)w < (unsigned)WW && f4 >= 1 && f4 <= 12) {
        v = *(const float4*)(x2 + ((c * HH + h) * WW + w) * DDD + (f4 - 1) * 4);
        const float inv = 1.0f / 32.0f;     // fold channel-mean into x2
        v.x *= inv; v.y *= inv; v.z *= inv; v.w *= inv;
    }
    *(float4*)(g_x2p + (size_t)idx * 4) = v;
}

__device__ __forceinline__ void fma2(ull& a, ull x, ull y) {
    asm("fma.rn.f32x2 %0, %1, %2, %0;" : "+l"(a) : "l"(x), "l"(y));
}
__device__ __forceinline__ void upk2(ull v, float& lo, float& hi) {
    asm("mov.b64 {%0, %1}, %2;" : "=f"(lo), "=f"(hi) : "l"(v));
}
// (hi32(a), lo32(b)) as packed f32x2 — register-pair select, 2 MOVs max.
__device__ __forceinline__ ull selpair(ull a, ull b) {
    float alo, ahi, blo, bhi;
    upk2(a, alo, ahi);
    upk2(b, blo, bhi);
    ull r;
    asm("mov.b64 %0, {%1, %2};" : "=l"(r) : "f"(ahi), "f"(blo));
    return r;
}

// Diagonal-blocked, barrier-free. CTA = (h, 8-row band of x2 rows, di, dj-triple).
// Thread t: chunk=t%12 -> d chunk D=4*chunk; rl=t/12 -> x2 row sp=s0+rl.
// Outputs (w_j = sp - dj0 - j, dj0+j), j=0..2, all 9 dk, 4 d voxels.
__global__ __launch_bounds__(96, 4)
void corr_kernel(const float* __restrict__ x1, float* __restrict__ out) {
    const int bx = blockIdx.x;          // 0..335
    const int h  = bx / 7;
    const int s0 = (bx % 7) * 8;
    const int by = blockIdx.y;          // 0..26
    const int di = by / 3;
    const int dj0 = (by % 3) * 3;

    const int t = threadIdx.x;          // 0..95
    const int chunk = t % 12;
    const int rl = t / 12;
    const int D = chunk * 4;
    const int sp = s0 + rl;             // padded w-row of x2, 0..55

    int wj[3];
    bool vj[3];
    const float* p1[3];
#pragma unroll
    for (int j = 0; j < 3; j++) {
        int w = sp - dj0 - j;
        wj[j] = w;
        vj[j] = ((unsigned)w < (unsigned)WW);
        int wc = min(WW - 1, max(0, w));
        p1[j] = x1 + (h * WW + wc) * DDD + D;
    }
    const float* p2 = g_x2p + ((h + di) * PDW + sp) * RD2 + D;   // window D..D+11 <= 56

    ull acc[3][2][9];
#pragma unroll
    for (int j = 0; j < 3; j++)
#pragma unroll
        for (int p = 0; p < 2; p++)
#pragma unroll
            for (int k = 0; k < 9; k++) acc[j][p][k] = 0ull;

    ulonglong2 A0[3], A1[3];
    ulonglong2 B0[3], B1[3];

// load current pointer positions, then advance pointers by one channel stride
#define LOADCH(Abuf, Bbuf)                                                         \
    do {                                                                           \
        Abuf[0] = *(const ulonglong2*)(p1[0]);                                     \
        Abuf[1] = *(const ulonglong2*)(p1[1]);                                     \
        Abuf[2] = *(const ulonglong2*)(p1[2]);                                     \
        Bbuf[0] = *(const ulonglong2*)(p2);                                        \
        Bbuf[1] = *(const ulonglong2*)(p2 + 4);                                    \
        Bbuf[2] = *(const ulonglong2*)(p2 + 8);                                    \
        p1[0] += X1_CSTRIDE; p1[1] += X1_CSTRIDE; p1[2] += X1_CSTRIDE;             \
        p2 += X2P_CSTRIDE;                                                         \
    } while (0)

#define COMPUTECH(Abuf, Bbuf)                                                      \
    do {                                                                           \
        ull P[6];                                                                  \
        P[0] = Bbuf[0].x; P[1] = Bbuf[0].y;                                        \
        P[2] = Bbuf[1].x; P[3] = Bbuf[1].y;                                        \
        P[4] = Bbuf[2].x; P[5] = Bbuf[2].y;                                        \
        ull S[5];                                                                  \
        S[0] = selpair(P[0], P[1]); S[1] = selpair(P[1], P[2]);                    \
        S[2] = selpair(P[2], P[3]); S[3] = selpair(P[3], P[4]);                    \
        S[4] = selpair(P[4], P[5]);                                                \
        _Pragma("unroll")                                                          \
        for (int j = 0; j < 3; j++) {                                              \
            const ull Aj0 = Abuf[j].x, Aj1 = Abuf[j].y;                            \
            _Pragma("unroll")                                                      \
            for (int dk = 0; dk < 9; dk++) {                                       \
                const int m = dk >> 1;                                             \
                if (dk & 1) {                                                      \
                    fma2(acc[j][0][dk], Aj0, S[m]);                                \
                    fma2(acc[j][1][dk], Aj1, S[m + 1]);                            \
                } else {                                                           \
                    fma2(acc[j][0][dk], Aj0, P[m]);                                \
                    fma2(acc[j][1][dk], Aj1, P[m + 1]);                            \
                }                                                                  \
            }                                                                      \
        }                                                                          \
    } while (0)

    LOADCH(A0, B0);
#pragma unroll 1
    for (int c = 0; c < CCH; c += 2) {
        LOADCH(A1, B1);
        COMPUTECH(A0, B0);
        if (c + 2 < CCH) LOADCH(A0, B0);
        COMPUTECH(A1, B1);
    }

    // epilogue: acc pairs ARE the outputs (mean folded into x2).
    // Streaming stores (write-once data): keep L2 for the input scratch.
#pragma unroll
    for (int j = 0; j < 3; j++) {
        if (!vj[j]) continue;
        const size_t ob = (size_t)((h * WW + wj[j]) * DDD + D);
        const int pl0 = (di * 9 + dj0 + j) * 9;
#pragma unroll
        for (int dk = 0; dk < 9; dk++) {
            ulonglong2 v;
            v.x = acc[j][0][dk];
            v.y = acc[j][1][dk];
            __stwt((ulonglong2*)(out + (size_t)(pl0 + dk) * OUT_CSTRIDE + ob), v);
        }
    }
}

extern "C" void kernel_launch(void* const* d_in, const int* in_sizes, int n_in,
                              void* d_out, int out_size) {
    const float* x1 = (const float*)d_in[0];
    const float* x2 = (const float*)d_in[1];
    float* out = (float*)d_out;

    const int t2 = CCH * PDW * PDW * (RD2 / 4);
    pad2_kernel<<<(t2 + 255) / 256, 256>>>(x2);

    dim3 grid(336, 27);   // (48 h * 7 s-bands), (9 di * 3 dj-triples)
    corr_kernel<<<grid, 96>>>(x1, out);
}

// round 17
// speedup vs baseline: 2.3654x; 1.0262x over previous
#include <cuda_runtime.h>

#define CCH 32
#define HH 48
#define WW 48
#define DDD 48
#define PDW 56
#define RD2 56                          // x2 scratch row length in floats (224B, packed)
#define X1_CSTRIDE (48 * 48 * 48)       // 110592
#define X2P_CSTRIDE (56 * 56 * RD2)     // 175616
#define OUT_CSTRIDE (48 * 48 * 48)      // 110592

typedef unsigned long long ull;

// Zero-padded x2 copy: (C, h+4, w+4, d'=d+4 in 56-float rows), PRE-SCALED by 1/32.
__device__ float g_x2p[CCH * PDW * PDW * RD2];

__global__ void pad2_kernel(const float* __restrict__ x2) {
    int idx = blockIdx.x * blockDim.x + threadIdx.x;
    const int total = CCH * PDW * PDW * (RD2 / 4);
    if (idx >= total) return;
    int f4 = idx % (RD2 / 4);
    int t = idx / (RD2 / 4);
    int wp = t % PDW; t /= PDW;
    int hp = t % PDW;
    int c = t / PDW;
    int w = wp - 4, h = hp - 4;
    float4 v = make_float4(0.f, 0.f, 0.f, 0.f);
    if ((unsigned)h < (unsigned)HH && (unsigned)w < (unsigned)WW && f4 >= 1 && f4 <= 12) {
        v = *(const float4*)(x2 + ((c * HH + h) * WW + w) * DDD + (f4 - 1) * 4);
        const float inv = 1.0f / 32.0f;     // fold channel-mean into x2
        v.x *= inv; v.y *= inv; v.z *= inv; v.w *= inv;
    }
    *(float4*)(g_x2p + (size_t)idx * 4) = v;
}

__device__ __forceinline__ void fma2(ull& a, ull x, ull y) {
    asm("fma.rn.f32x2 %0, %1, %2, %0;" : "+l"(a) : "l"(x), "l"(y));
}
__device__ __forceinline__ void upk2(ull v, float& lo, float& hi) {
    asm("mov.b64 {%0, %1}, %2;" : "=f"(lo), "=f"(hi) : "l"(v));
}
// (hi32(a), lo32(b)) as packed f32x2 — register-pair select, 2 MOVs max.
__device__ __forceinline__ ull selpair(ull a, ull b) {
    float alo, ahi, blo, bhi;
    upk2(a, alo, ahi);
    upk2(b, blo, bhi);
    ull r;
    asm("mov.b64 %0, {%1, %2};" : "=l"(r) : "f"(ahi), "f"(blo));
    return r;
}

// Diagonal-blocked, barrier-free. CTA = (h, 8-row band of x2 rows, di, dj-triple).
// Thread t: chunk=t%12 -> d chunk D=4*chunk; rl=t/12 -> x2 row sp=s0+rl.
// Outputs (w_j = sp - dj0 - j, dj0+j), j=0..2, all 9 dk, 4 d voxels.
__global__ __launch_bounds__(96, 4)
void corr_kernel(const float* __restrict__ x1, float* __restrict__ out) {
    const int bx = blockIdx.x;          // 0..335
    const int h  = bx / 7;
    const int s0 = (bx % 7) * 8;
    const int by = blockIdx.y;          // 0..26
    const int di = by / 3;
    const int dj0 = (by % 3) * 3;

    const int t = threadIdx.x;          // 0..95
    const int chunk = t % 12;
    const int rl = t / 12;
    const int D = chunk * 4;
    const int sp = s0 + rl;             // padded w-row of x2, 0..55

    int wj[3];
    bool vj[3];
    const float* p1[3];
#pragma unroll
    for (int j = 0; j < 3; j++) {
        int w = sp - dj0 - j;
        wj[j] = w;
        vj[j] = ((unsigned)w < (unsigned)WW);
        int wc = min(WW - 1, max(0, w));
        p1[j] = x1 + (h * WW + wc) * DDD + D;
    }
    const float* p2 = g_x2p + ((h + di) * PDW + sp) * RD2 + D;   // window D..D+11 <= 56

    ull acc[3][2][9];
#pragma unroll
    for (int j = 0; j < 3; j++)
#pragma unroll
        for (int p = 0; p < 2; p++)
#pragma unroll
            for (int k = 0; k < 9; k++) acc[j][p][k] = 0ull;

    ulonglong2 A0[3], A1[3];
    ulonglong2 B0[3], B1[3];

// load current pointer positions, then advance pointers by one channel stride
#define LOADCH(Abuf, Bbuf)                                                         \
    do {                                                                           \
        Abuf[0] = *(const ulonglong2*)(p1[0]);                                     \
        Abuf[1] = *(const ulonglong2*)(p1[1]);                                     \
        Abuf[2] = *(const ulonglong2*)(p1[2]);                                     \
        Bbuf[0] = *(const ulonglong2*)(p2);                                        \
        Bbuf[1] = *(const ulonglong2*)(p2 + 4);                                    \
        Bbuf[2] = *(const ulonglong2*)(p2 + 8);                                    \
        p1[0] += X1_CSTRIDE; p1[1] += X1_CSTRIDE; p1[2] += X1_CSTRIDE;             \
        p2 += X2P_CSTRIDE;                                                         \
    } while (0)

#define COMPUTECH(Abuf, Bbuf)                                                      \
    do {                                                                           \
        ull P[6];                                                                  \
        P[0] = Bbuf[0].x; P[1] = Bbuf[0].y;                                        \
        P[2] = Bbuf[1].x; P[3] = Bbuf[1].y;                                        \
        P[4] = Bbuf[2].x; P[5] = Bbuf[2].y;                                        \
        ull S[5];                                                                  \
        S[0] = selpair(P[0], P[1]); S[1] = selpair(P[1], P[2]);                    \
        S[2] = selpair(P[2], P[3]); S[3] = selpair(P[3], P[4]);                    \
        S[4] = selpair(P[4], P[5]);                                                \
        _Pragma("unroll")                                                          \
        for (int j = 0; j < 3; j++) {                                              \
            const ull Aj0 = Abuf[j].x, Aj1 = Abuf[j].y;                            \
            _Pragma("unroll")                                                      \
            for (int dk = 0; dk < 9; dk++) {                                       \
                const int m = dk >> 1;                                             \
                if (dk & 1) {                                                      \
                    fma2(acc[j][0][dk], Aj0, S[m]);                                \
                    fma2(acc[j][1][dk], Aj1, S[m + 1]);                            \
                } else {                                                           \
                    fma2(acc[j][0][dk], Aj0, P[m]);                                \
                    fma2(acc[j][1][dk], Aj1, P[m + 1]);                            \
                }                                                                  \
            }                                                                      \
        }                                                                          \
    } while (0)

    LOADCH(A0, B0);
#pragma unroll 1
    for (int c = 0; c < CCH; c += 2) {
        LOADCH(A1, B1);
        COMPUTECH(A0, B0);
        if (c + 2 < CCH) LOADCH(A0, B0);
        COMPUTECH(A1, B1);
    }

    // epilogue: acc pairs ARE the outputs (mean folded into x2). Plain cached stores.
#pragma unroll
    for (int j = 0; j < 3; j++) {
        if (!vj[j]) continue;
        const size_t ob = (size_t)((h * WW + wj[j]) * DDD + D);
        const int pl0 = (di * 9 + dj0 + j) * 9;
#pragma unroll
        for (int dk = 0; dk < 9; dk++) {
            ulonglong2 v;
            v.x = acc[j][0][dk];
            v.y = acc[j][1][dk];
            *(ulonglong2*)(out + (size_t)(pl0 + dk) * OUT_CSTRIDE + ob) = v;
        }
    }
}

extern "C" void kernel_launch(void* const* d_in, const int* in_sizes, int n_in,
                              void* d_out, int out_size) {
    const float* x1 = (const float*)d_in[0];
    const float* x2 = (const float*)d_in[1];
    float* out = (float*)d_out;

    const int t2 = CCH * PDW * PDW * (RD2 / 4);
    pad2_kernel<<<(t2 + 255) / 256, 256>>>(x2);

    dim3 grid(336, 27);   // (48 h * 7 s-bands), (9 di * 3 dj-triples)
    corr_kernel<<<grid, 96>>>(x1, out);
}